// round 9
// baseline (speedup 1.0000x reference)
#include <cuda_runtime.h>

#define TM      16
#define NTH     256
#define DSTATE  256
#define DIN     512
#define NW      512
#define NSTEPS  60
#define NBLOCKS 128

typedef unsigned long long u64;

__constant__ float c_A[6][5] = {
    {0.f, 0.f, 0.f, 0.f, 0.f},
    {0.161f, 0.f, 0.f, 0.f, 0.f},
    {-0.008480655492356989f, 0.335480655492357f, 0.f, 0.f, 0.f},
    {2.8971530571054935f, -6.359448489975075f, 4.3622954328695815f, 0.f, 0.f},
    {5.325864828439257f, -11.748883564062828f, 7.4955393428898365f, -0.09249506636175525f, 0.f},
    {5.86145544294642f, -12.92096931784711f, 8.159367898576159f, -0.071584973281401f, -0.028269050394068383f}};
__constant__ float c_Bw[6] = {
    0.09646076681806523f, 0.01f, 0.4798896504144996f,
    1.379008574103742f, -3.290069515436081f, 2.324710524099774f};

// +4 rows pad: weight prefetch overreads up to 2 k-rows at the loop tail.
__device__ float g_W1T[(DIN + 4) * NW];
__device__ float g_W2T[(NW + 4) * NW];
__device__ float g_W3T[(NW + 4) * DSTATE];
__device__ float g_BU[NBLOCKS * NW * TM];          // b1 + W1[:,256:]@u per CTA
__device__ float g_KB[NBLOCKS * 6 * DSTATE * TM];  // stage derivatives (L2-resident)

// ---------------- packed f32x2 helpers ----------------
static __device__ __forceinline__ u64 pk2(float x, float y) {
    u64 d; asm("mov.b64 %0, {%1, %2};" : "=l"(d) : "f"(x), "f"(y)); return d;
}
static __device__ __forceinline__ u64 fma2(u64 a, u64 b, u64 c) {
    u64 d; asm("fma.rn.f32x2 %0, %1, %2, %3;" : "=l"(d) : "l"(a), "l"(b), "l"(c)); return d;
}

// ---------------- weight transpose: src[N][K] -> dst[K][N] ----------------
__global__ void transpose_kernel(int which, const float* __restrict__ src, int N, int K) {
    float* dst = (which == 0) ? g_W1T : (which == 1) ? g_W2T : g_W3T;
    __shared__ float tile[32][33];
    int kb = blockIdx.x * 32, nb = blockIdx.y * 32;
    int tx = threadIdx.x, ty = threadIdx.y;
    #pragma unroll
    for (int i = ty; i < 32; i += 8) tile[i][tx] = src[(nb + i) * K + (kb + tx)];
    __syncthreads();
    #pragma unroll
    for (int i = ty; i < 32; i += 8) dst[(kb + i) * N + (nb + tx)] = tile[tx][i];
}

// ---------------- 16m x 8n register-tile GEMM (acc = 64 u64 = 128 floats) ---
// Full 16-row m tile (m0 = 0 for every thread). A JIT from SMEM (4 broadcast
// LDS.128 per k); W prefetched 2 k ahead (covers L2 latency at 2 warps/SMSP).
static __device__ __forceinline__ void cmpk16(const float* __restrict__ Asm, int k,
                                              const float4& wa, const float4& wb,
                                              u64* __restrict__ acc) {
    const ulonglong2* ap = reinterpret_cast<const ulonglong2*>(Asm + k * TM);
    ulonglong2 a0 = ap[0], a1 = ap[1], a2 = ap[2], a3 = ap[3];  // 16 m floats
    float wv[8] = {wa.x, wa.y, wa.z, wa.w, wb.x, wb.y, wb.z, wb.w};
    #pragma unroll
    for (int nj = 0; nj < 8; ++nj) {
        u64 wd = pk2(wv[nj], wv[nj]);
        acc[nj * 8 + 0] = fma2(a0.x, wd, acc[nj * 8 + 0]);
        acc[nj * 8 + 1] = fma2(a0.y, wd, acc[nj * 8 + 1]);
        acc[nj * 8 + 2] = fma2(a1.x, wd, acc[nj * 8 + 2]);
        acc[nj * 8 + 3] = fma2(a1.y, wd, acc[nj * 8 + 3]);
        acc[nj * 8 + 4] = fma2(a2.x, wd, acc[nj * 8 + 4]);
        acc[nj * 8 + 5] = fma2(a2.y, wd, acc[nj * 8 + 5]);
        acc[nj * 8 + 6] = fma2(a3.x, wd, acc[nj * 8 + 6]);
        acc[nj * 8 + 7] = fma2(a3.y, wd, acc[nj * 8 + 7]);
    }
}

// KH multiple of 2. W prefetch overreads rows KH..KH+1 (padded arrays).
// Activations read strictly within [0, KH) rows of Asm.
static __device__ __forceinline__ void mma16x8(
    const float* __restrict__ Asm, const float* __restrict__ Wg,
    int ldw, int KH, u64* __restrict__ acc) {
    float4 wa0 = *reinterpret_cast<const float4*>(Wg);
    float4 wb0 = *reinterpret_cast<const float4*>(Wg + 4);
    float4 wa1 = *reinterpret_cast<const float4*>(Wg + (size_t)ldw);
    float4 wb1 = *reinterpret_cast<const float4*>(Wg + (size_t)ldw + 4);
    #pragma unroll 1
    for (int k = 0; k < KH; k += 2) {
        const float* nw0 = Wg + (size_t)(k + 2) * ldw;
        const float* nw1 = Wg + (size_t)(k + 3) * ldw;
        float4 na0 = *reinterpret_cast<const float4*>(nw0);
        float4 nb0 = *reinterpret_cast<const float4*>(nw0 + 4);
        float4 na1 = *reinterpret_cast<const float4*>(nw1);
        float4 nb1 = *reinterpret_cast<const float4*>(nw1 + 4);
        cmpk16(Asm, k, wa0, wb0, acc);
        cmpk16(Asm, k + 1, wa1, wb1, acc);
        wa0 = na0; wb0 = nb0; wa1 = na1; wb1 = nb1;
    }
}

static __device__ __forceinline__ void store_partial16(
    float* __restrict__ dst, int n0, const u64* __restrict__ acc) {
    #pragma unroll
    for (int nj = 0; nj < 8; ++nj) {
        float* row = dst + (n0 + nj) * TM;
        #pragma unroll
        for (int h = 0; h < 4; ++h) {
            ulonglong2 v;
            v.x = acc[nj * 8 + h * 2];
            v.y = acc[nj * 8 + h * 2 + 1];
            *reinterpret_cast<ulonglong2*>(row + h * 4) = v;
        }
    }
}

static __device__ __forceinline__ void zero64(u64* acc) {
    #pragma unroll
    for (int i = 0; i < 64; ++i) acc[i] = 0ull;
}

// ---------------- main fused Tsit5 kernel ----------------
__global__ void __launch_bounds__(NTH, 1)
ode_main(const float* __restrict__ x0, const float* __restrict__ uf,
         const float* __restrict__ b1, const float* __restrict__ b2,
         const float* __restrict__ b3, float* __restrict__ out) {
    extern __shared__ float smem[];
    float* A0 = smem;                 // [512][16] z (rows 0-255) / gemm2 out+q0 partial
    float* A1 = A0 + NW * TM;         // [512][16] gemm1 out+q0 / gemm3 partials 0,1
    float* P1 = A1 + NW * TM;         // [512][16] x3 contiguous: q1..q3 / gemm3 2..7
    float* Y  = P1 + 3 * NW * TM;     // [256][16]

    const int tid = threadIdx.x;
    const int r0 = blockIdx.x * TM;
    float* BUg = g_BU + (size_t)blockIdx.x * (NW * TM);
    float* gKB = g_KB + (size_t)blockIdx.x * (6 * DSTATE * TM);

    // N=512 gemms: 4-way k-split, 64 n-positions (full-m tile)
    const int q4 = tid >> 6;              // 0..3
    const int n0 = (tid & 63) * 8;
    // gemm3 (N=256): 8-way k-split, 32 n-positions
    const int q8 = tid >> 5;              // 0..7
    const int n8 = (tid & 31) * 8;

    // branchless partial destinations (computed once)
    float* pdst4_1 = q4 ? (P1 + (size_t)(q4 - 1) * (NW * TM)) : A1;  // gemm1 (out A1)
    float* pdst4_2 = q4 ? (P1 + (size_t)(q4 - 1) * (NW * TM)) : A0;  // gemm2 (out A0)
    float* pdst8   = (q8 < 2) ? (A1 + (size_t)q8 * (DSTATE * TM))
                              : (P1 + (size_t)(q8 - 2) * (DSTATE * TM));  // gemm3

    // init Y; u into A0 rows 0-255 (k-major) for BU precompute
    for (int idx = tid; idx < TM * DSTATE; idx += NTH) {
        int m = idx >> 8, c = idx & 255;
        int r = r0 + m, traj = r & 1023;
        Y[c * TM + m] = x0[traj * DSTATE + c];
        A0[c * TM + m] = (r < 1024) ? uf[traj * DSTATE + c] : 0.f;
    }
    __syncthreads();

    // ---- BU = b1 + W1[:,256:512] @ u  (K=256, 4-way split) ----
    {
        u64 acc[64];
        zero64(acc);
        mma16x8(A0 + q4 * 64 * TM,
                g_W1T + (size_t)(DSTATE + q4 * 64) * NW + n0, NW, 64, acc);
        store_partial16(pdst4_1, n0, acc);
        __syncthreads();
        for (int i4 = tid; i4 < (NW * TM) / 4; i4 += NTH) {
            float4 a  = reinterpret_cast<const float4*>(A1)[i4];
            float4 p1 = reinterpret_cast<const float4*>(P1)[i4];
            float4 p2 = reinterpret_cast<const float4*>(P1 + NW * TM)[i4];
            float4 p3 = reinterpret_cast<const float4*>(P1 + 2 * NW * TM)[i4];
            float bb = b1[i4 >> 2];
            reinterpret_cast<float4*>(BUg)[i4] = make_float4(
                a.x + p1.x + p2.x + p3.x + bb, a.y + p1.y + p2.y + p3.y + bb,
                a.z + p1.z + p2.z + p3.z + bb, a.w + p1.w + p2.w + p3.w + bb);
        }
        __syncthreads();
    }

    const float H = 1.0f / 60.0f;

    #pragma unroll 1
    for (int step = 0; step < NSTEPS; ++step) {
        #pragma unroll 1
        for (int s = 0; s < 6; ++s) {
            // build z = y + H * sum_j a_sj k_j -> A0 rows [0,256)
            for (int i4 = tid; i4 < (DSTATE * TM) / 4; i4 += NTH) {
                float4 y = reinterpret_cast<const float4*>(Y)[i4];
                float4 a = make_float4(0.f, 0.f, 0.f, 0.f);
                for (int j = 0; j < s; ++j) {
                    float4 kv = reinterpret_cast<const float4*>(gKB + j * DSTATE * TM)[i4];
                    float aj = c_A[s][j];
                    a.x += aj * kv.x; a.y += aj * kv.y;
                    a.z += aj * kv.z; a.w += aj * kv.w;
                }
                y.x += H * a.x; y.y += H * a.y; y.z += H * a.z; y.w += H * a.w;
                reinterpret_cast<float4*>(A0)[i4] = y;
            }
            __syncthreads();

            // gemm1: A1 = relu(BU + W1[:, :256] @ z), K=256, 4-way split
            {
                u64 acc[64];
                zero64(acc);
                mma16x8(A0 + q4 * 64 * TM,
                        g_W1T + (size_t)(q4 * 64) * NW + n0, NW, 64, acc);
                store_partial16(pdst4_1, n0, acc);
                __syncthreads();
                for (int i4 = tid; i4 < (NW * TM) / 4; i4 += NTH) {
                    float4 a  = reinterpret_cast<const float4*>(A1)[i4];
                    float4 p1 = reinterpret_cast<const float4*>(P1)[i4];
                    float4 p2 = reinterpret_cast<const float4*>(P1 + NW * TM)[i4];
                    float4 p3 = reinterpret_cast<const float4*>(P1 + 2 * NW * TM)[i4];
                    float4 bu = reinterpret_cast<const float4*>(BUg)[i4];
                    float4 v;
                    v.x = fmaxf(a.x + p1.x + p2.x + p3.x + bu.x, 0.f);
                    v.y = fmaxf(a.y + p1.y + p2.y + p3.y + bu.y, 0.f);
                    v.z = fmaxf(a.z + p1.z + p2.z + p3.z + bu.z, 0.f);
                    v.w = fmaxf(a.w + p1.w + p2.w + p3.w + bu.w, 0.f);
                    reinterpret_cast<float4*>(A1)[i4] = v;
                }
                __syncthreads();
            }
            // gemm2: A0 = relu(b2 + W2 @ h1), K=512, 4-way split
            {
                u64 acc[64];
                zero64(acc);
                mma16x8(A1 + q4 * 128 * TM,
                        g_W2T + (size_t)(q4 * 128) * NW + n0, NW, 128, acc);
                store_partial16(pdst4_2, n0, acc);
                __syncthreads();
                for (int i4 = tid; i4 < (NW * TM) / 4; i4 += NTH) {
                    float4 a  = reinterpret_cast<const float4*>(A0)[i4];
                    float4 p1 = reinterpret_cast<const float4*>(P1)[i4];
                    float4 p2 = reinterpret_cast<const float4*>(P1 + NW * TM)[i4];
                    float4 p3 = reinterpret_cast<const float4*>(P1 + 2 * NW * TM)[i4];
                    float bb = b2[i4 >> 2];
                    float4 v;
                    v.x = fmaxf(a.x + p1.x + p2.x + p3.x + bb, 0.f);
                    v.y = fmaxf(a.y + p1.y + p2.y + p3.y + bb, 0.f);
                    v.z = fmaxf(a.z + p1.z + p2.z + p3.z + bb, 0.f);
                    v.w = fmaxf(a.w + p1.w + p2.w + p3.w + bb, 0.f);
                    reinterpret_cast<float4*>(A0)[i4] = v;
                }
                __syncthreads();
            }
            // gemm3: k_s = b3 + W3 @ h2, K=512, N=256, 8-way split
            {
                u64 acc[64];
                zero64(acc);
                mma16x8(A0 + q8 * 64 * TM,
                        g_W3T + (size_t)(q8 * 64) * DSTATE + n8, DSTATE, 64, acc);
                store_partial16(pdst8, n8, acc);
                __syncthreads();
                float* KBs = gKB + s * DSTATE * TM;
                for (int i4 = tid; i4 < (DSTATE * TM) / 4; i4 += NTH) {
                    float bb = b3[i4 >> 2];
                    float4 v = make_float4(bb, bb, bb, bb);
                    #pragma unroll
                    for (int o = 0; o < 2; ++o) {
                        float4 p = reinterpret_cast<const float4*>(A1 + o * DSTATE * TM)[i4];
                        v.x += p.x; v.y += p.y; v.z += p.z; v.w += p.w;
                    }
                    #pragma unroll
                    for (int o = 0; o < 6; ++o) {
                        float4 p = reinterpret_cast<const float4*>(P1 + o * DSTATE * TM)[i4];
                        v.x += p.x; v.y += p.y; v.z += p.z; v.w += p.w;
                    }
                    reinterpret_cast<float4*>(KBs)[i4] = v;
                }
                __syncthreads();
            }
        }
        // y += H * sum_i b_i k_i
        for (int i4 = tid; i4 < (DSTATE * TM) / 4; i4 += NTH) {
            float4 y = reinterpret_cast<const float4*>(Y)[i4];
            float4 a = make_float4(0.f, 0.f, 0.f, 0.f);
            #pragma unroll
            for (int j = 0; j < 6; ++j) {
                float4 kv = reinterpret_cast<const float4*>(gKB + j * DSTATE * TM)[i4];
                float bj = c_Bw[j];
                a.x += bj * kv.x; a.y += bj * kv.y;
                a.z += bj * kv.z; a.w += bj * kv.w;
            }
            y.x += H * a.x; y.y += H * a.y; y.z += H * a.z; y.w += H * a.w;
            reinterpret_cast<float4*>(Y)[i4] = y;
        }
        __syncthreads();
    }

    for (int idx = tid; idx < TM * DSTATE; idx += NTH) {
        int m = idx >> 8, c = idx & 255;
        out[(size_t)(r0 + m) * DSTATE + c] = Y[c * TM + m];
    }
}

// ---------------- launch ----------------
extern "C" void kernel_launch(void* const* d_in, const int* in_sizes, int n_in,
                              void* d_out, int out_size) {
    (void)in_sizes; (void)n_in; (void)out_size;
    const float* x0 = (const float*)d_in[0];
    const float* uf = (const float*)d_in[1];
    const float* W1 = (const float*)d_in[2];
    const float* b1 = (const float*)d_in[3];
    const float* W2 = (const float*)d_in[4];
    const float* b2 = (const float*)d_in[5];
    const float* W3 = (const float*)d_in[6];
    const float* b3 = (const float*)d_in[7];
    float* out = (float*)d_out;

    dim3 tthreads(32, 8);
    transpose_kernel<<<dim3(DIN / 32, NW / 32), tthreads>>>(0, W1, NW, DIN);
    transpose_kernel<<<dim3(NW / 32, NW / 32), tthreads>>>(1, W2, NW, NW);
    transpose_kernel<<<dim3(NW / 32, DSTATE / 32), tthreads>>>(2, W3, DSTATE, NW);

    size_t smem_bytes = (size_t)(5 * NW * TM + DSTATE * TM) * sizeof(float);
    cudaFuncSetAttribute(ode_main, cudaFuncAttributeMaxDynamicSharedMemorySize, (int)smem_bytes);
    ode_main<<<NBLOCKS, NTH, smem_bytes>>>(x0, uf, b1, b2, b3, out);
}

// round 10
// speedup vs baseline: 1.3954x; 1.3954x over previous
#include <cuda_runtime.h>

#define TM      16
#define NTH     256
#define DSTATE  256
#define DIN     512
#define NW      512
#define NSTEPS  60
#define NBLOCKS 128

typedef unsigned long long u64;

__constant__ float c_A[6][5] = {
    {0.f, 0.f, 0.f, 0.f, 0.f},
    {0.161f, 0.f, 0.f, 0.f, 0.f},
    {-0.008480655492356989f, 0.335480655492357f, 0.f, 0.f, 0.f},
    {2.8971530571054935f, -6.359448489975075f, 4.3622954328695815f, 0.f, 0.f},
    {5.325864828439257f, -11.748883564062828f, 7.4955393428898365f, -0.09249506636175525f, 0.f},
    {5.86145544294642f, -12.92096931784711f, 8.159367898576159f, -0.071584973281401f, -0.028269050394068383f}};
__constant__ float c_Bw[6] = {
    0.09646076681806523f, 0.01f, 0.4798896504144996f,
    1.379008574103742f, -3.290069515436081f, 2.324710524099774f};

// +4 rows of padding: the 4-deep weight prefetch overreads up to 4 k-rows
// at the loop tail (values never consumed).
__device__ float g_W1T[(DIN + 4) * NW];
__device__ float g_W2T[(NW + 4) * NW];
__device__ float g_W3T[(NW + 4) * DSTATE];
__device__ float g_BU[NBLOCKS * NW * TM];   // per-CTA b1 + W1[:,256:]@u

// ---------------- packed f32x2 helpers ----------------
static __device__ __forceinline__ u64 pk2(float x, float y) {
    u64 d; asm("mov.b64 %0, {%1, %2};" : "=l"(d) : "f"(x), "f"(y)); return d;
}
static __device__ __forceinline__ u64 fma2(u64 a, u64 b, u64 c) {
    u64 d; asm("fma.rn.f32x2 %0, %1, %2, %3;" : "=l"(d) : "l"(a), "l"(b), "l"(c)); return d;
}

// ---------------- weight transpose: src[N][K] -> dst[K][N] ----------------
__global__ void transpose_kernel(int which, const float* __restrict__ src, int N, int K) {
    float* dst = (which == 0) ? g_W1T : (which == 1) ? g_W2T : g_W3T;
    __shared__ float tile[32][33];
    int kb = blockIdx.x * 32, nb = blockIdx.y * 32;
    int tx = threadIdx.x, ty = threadIdx.y;
    #pragma unroll
    for (int i = ty; i < 32; i += 8) tile[i][tx] = src[(nb + i) * K + (kb + tx)];
    __syncthreads();
    #pragma unroll
    for (int i = ty; i < 32; i += 8) dst[(kb + i) * N + (nb + tx)] = tile[tx][i];
}

// ---------------- 8m x 8n register-tile GEMM ----------------
// Weights prefetched 4 k ahead (covers ~262-cyc L2 latency at 2 warps/SMSP);
// activations loaded JIT from SMEM (29-cyc LDS).
struct W8 { float4 a, b; };

static __device__ __forceinline__ W8 ldw8(const float* __restrict__ Wg, int ldw, int k) {
    W8 w;
    const float* r = Wg + (size_t)k * ldw;
    w.a = *reinterpret_cast<const float4*>(r);
    w.b = *reinterpret_cast<const float4*>(r + 4);
    return w;
}

static __device__ __forceinline__ void cmpA(const float* __restrict__ Asm, int k,
                                            const W8& w, u64* __restrict__ acc) {
    ulonglong2 a0 = *reinterpret_cast<const ulonglong2*>(Asm + k * TM);
    ulonglong2 a1 = *reinterpret_cast<const ulonglong2*>(Asm + k * TM + 4);
    float wv[8] = {w.a.x, w.a.y, w.a.z, w.a.w, w.b.x, w.b.y, w.b.z, w.b.w};
    #pragma unroll
    for (int nj = 0; nj < 8; ++nj) {
        u64 wd = pk2(wv[nj], wv[nj]);
        acc[nj * 4 + 0] = fma2(a0.x, wd, acc[nj * 4 + 0]);
        acc[nj * 4 + 1] = fma2(a0.y, wd, acc[nj * 4 + 1]);
        acc[nj * 4 + 2] = fma2(a1.x, wd, acc[nj * 4 + 2]);
        acc[nj * 4 + 3] = fma2(a1.y, wd, acc[nj * 4 + 3]);
    }
}

// KH must be a multiple of 4. Weight prefetch overreads rows KH..KH+3
// (padded device arrays). Activations read strictly within [0, KH).
static __device__ __forceinline__ void mma8x8(
    const float* __restrict__ Asm, const float* __restrict__ Wg,
    int ldw, int KH, u64* __restrict__ acc) {
    W8 w0 = ldw8(Wg, ldw, 0);
    W8 w1 = ldw8(Wg, ldw, 1);
    W8 w2 = ldw8(Wg, ldw, 2);
    W8 w3 = ldw8(Wg, ldw, 3);
    #pragma unroll 1
    for (int k = 0; k < KH; k += 4) {
        cmpA(Asm, k + 0, w0, acc); w0 = ldw8(Wg, ldw, k + 4);
        cmpA(Asm, k + 1, w1, acc); w1 = ldw8(Wg, ldw, k + 5);
        cmpA(Asm, k + 2, w2, acc); w2 = ldw8(Wg, ldw, k + 6);
        cmpA(Asm, k + 3, w3, acc); w3 = ldw8(Wg, ldw, k + 7);
    }
}

static __device__ __forceinline__ void store_partial(
    float* __restrict__ dst, int n0, int m0, const u64* __restrict__ acc) {
    #pragma unroll
    for (int nj = 0; nj < 8; ++nj) {
        ulonglong2 v, w;
        v.x = acc[nj * 4 + 0]; v.y = acc[nj * 4 + 1];
        w.x = acc[nj * 4 + 2]; w.y = acc[nj * 4 + 3];
        *reinterpret_cast<ulonglong2*>(dst + (n0 + nj) * TM + m0) = v;
        *reinterpret_cast<ulonglong2*>(dst + (n0 + nj) * TM + m0 + 4) = w;
    }
}

static __device__ __forceinline__ void zero_acc(u64* acc) {
    #pragma unroll
    for (int i = 0; i < 32; ++i) acc[i] = 0ull;
}

// ---------------- main fused Tsit5 kernel ----------------
__global__ void __launch_bounds__(NTH, 1)
ode_main(const float* __restrict__ x0, const float* __restrict__ uf,
         const float* __restrict__ b1, const float* __restrict__ b2,
         const float* __restrict__ b3, float* __restrict__ out) {
    extern __shared__ float smem[];
    float* A0 = smem;                 // [512][16]
    float* A1 = A0 + NW * TM;         // [512][16]
    float* P  = A1 + NW * TM;         // [512][16]
    float* Y  = P + NW * TM;          // [256][16]
    float* KB = Y + DSTATE * TM;      // [6][256][16]

    const int tid = threadIdx.x;
    const int r0 = blockIdx.x * TM;
    float* BUg = g_BU + (size_t)blockIdx.x * (NW * TM);

    // N=512 gemms: 2-way k-split, 128 positions (2m x 64n)
    const int half = tid >> 7;
    const int pos = tid & 127;
    const int m0 = (pos & 1) * 8;
    const int n0 = (pos >> 1) * 8;
    // gemm3 (N=256): 4-way k-split, 64 positions
    const int q = tid >> 6;
    const int pos3 = tid & 63;
    const int m3 = (pos3 & 1) * 8;
    const int n3 = (pos3 >> 1) * 8;

    // init Y; u into A0 rows 0-255 (k-major) for BU precompute
    for (int idx = tid; idx < TM * DSTATE; idx += NTH) {
        int m = idx >> 8, c = idx & 255;
        int r = r0 + m, traj = r & 1023;
        Y[c * TM + m] = x0[traj * DSTATE + c];
        A0[c * TM + m] = (r < 1024) ? uf[traj * DSTATE + c] : 0.f;
    }
    __syncthreads();

    // ---- BU = b1 + W1[:,256:512] @ u ----
    {
        u64 acc[32];
        zero_acc(acc);
        mma8x8(A0 + half * 128 * TM + m0,
               g_W1T + (size_t)(DSTATE + half * 128) * NW + n0, NW, 128, acc);
        store_partial(half ? P : A1, n0, m0, acc);
        __syncthreads();
        for (int i4 = tid; i4 < (NW * TM) / 4; i4 += NTH) {
            float4 a = reinterpret_cast<const float4*>(A1)[i4];
            float4 p = reinterpret_cast<const float4*>(P)[i4];
            float bb = b1[i4 >> 2];
            reinterpret_cast<float4*>(BUg)[i4] =
                make_float4(a.x + p.x + bb, a.y + p.y + bb, a.z + p.z + bb, a.w + p.w + bb);
        }
        __syncthreads();
    }

    const float H = 1.0f / 60.0f;

    #pragma unroll 1
    for (int step = 0; step < NSTEPS; ++step) {
        #pragma unroll 1
        for (int s = 0; s < 6; ++s) {
            // z = y + H * sum_j a_sj k_j  -> A0 rows [0,256)
            for (int i4 = tid; i4 < (DSTATE * TM) / 4; i4 += NTH) {
                float4 y = reinterpret_cast<const float4*>(Y)[i4];
                float4 a = make_float4(0.f, 0.f, 0.f, 0.f);
                for (int j = 0; j < s; ++j) {
                    float4 kv = reinterpret_cast<const float4*>(KB + j * DSTATE * TM)[i4];
                    float aj = c_A[s][j];
                    a.x += aj * kv.x; a.y += aj * kv.y;
                    a.z += aj * kv.z; a.w += aj * kv.w;
                }
                y.x += H * a.x; y.y += H * a.y; y.z += H * a.z; y.w += H * a.w;
                reinterpret_cast<float4*>(A0)[i4] = y;
            }
            __syncthreads();

            // gemm1: A1 = relu(BU + W1[:, :256] @ z), K=256, 2-way k-split
            {
                u64 acc[32];
                zero_acc(acc);
                mma8x8(A0 + half * 128 * TM + m0,
                       g_W1T + (size_t)(half * 128) * NW + n0, NW, 128, acc);
                store_partial(half ? P : A1, n0, m0, acc);
                __syncthreads();
                for (int i4 = tid; i4 < (NW * TM) / 4; i4 += NTH) {
                    float4 a = reinterpret_cast<const float4*>(A1)[i4];
                    float4 p = reinterpret_cast<const float4*>(P)[i4];
                    float4 bu = reinterpret_cast<const float4*>(BUg)[i4];
                    float4 v;
                    v.x = fmaxf(a.x + p.x + bu.x, 0.f);
                    v.y = fmaxf(a.y + p.y + bu.y, 0.f);
                    v.z = fmaxf(a.z + p.z + bu.z, 0.f);
                    v.w = fmaxf(a.w + p.w + bu.w, 0.f);
                    reinterpret_cast<float4*>(A1)[i4] = v;
                }
                __syncthreads();
            }
            // gemm2: A0 = relu(b2 + W2 @ h1), K=512, 2-way k-split
            {
                u64 acc[32];
                zero_acc(acc);
                mma8x8(A1 + half * 256 * TM + m0,
                       g_W2T + (size_t)(half * 256) * NW + n0, NW, 256, acc);
                store_partial(half ? P : A0, n0, m0, acc);
                __syncthreads();
                for (int i4 = tid; i4 < (NW * TM) / 4; i4 += NTH) {
                    float4 a = reinterpret_cast<const float4*>(A0)[i4];
                    float4 p = reinterpret_cast<const float4*>(P)[i4];
                    float bb = b2[i4 >> 2];
                    float4 v;
                    v.x = fmaxf(a.x + p.x + bb, 0.f);
                    v.y = fmaxf(a.y + p.y + bb, 0.f);
                    v.z = fmaxf(a.z + p.z + bb, 0.f);
                    v.w = fmaxf(a.w + p.w + bb, 0.f);
                    reinterpret_cast<float4*>(A0)[i4] = v;
                }
                __syncthreads();
            }
            // gemm3: k_s = b3 + W3 @ h2, K=512, N=256, 4-way k-split
            {
                float* KBs = KB + s * DSTATE * TM;
                u64 acc[32];
                zero_acc(acc);
                mma8x8(A0 + q * 128 * TM + m3,
                       g_W3T + (size_t)(q * 128) * DSTATE + n3, DSTATE, 128, acc);
                float* pdst = (q == 0) ? KBs : (q == 1) ? P : (q == 2) ? (P + DSTATE * TM) : A1;
                store_partial(pdst, n3, m3, acc);
                __syncthreads();
                for (int i4 = tid; i4 < (DSTATE * TM) / 4; i4 += NTH) {
                    float4 a  = reinterpret_cast<const float4*>(KBs)[i4];
                    float4 p1 = reinterpret_cast<const float4*>(P)[i4];
                    float4 p2 = reinterpret_cast<const float4*>(P + DSTATE * TM)[i4];
                    float4 p3 = reinterpret_cast<const float4*>(A1)[i4];
                    float bb = b3[i4 >> 2];
                    float4 v;
                    v.x = a.x + p1.x + p2.x + p3.x + bb;
                    v.y = a.y + p1.y + p2.y + p3.y + bb;
                    v.z = a.z + p1.z + p2.z + p3.z + bb;
                    v.w = a.w + p1.w + p2.w + p3.w + bb;
                    reinterpret_cast<float4*>(KBs)[i4] = v;
                }
                __syncthreads();
            }
        }
        // y += H * sum_i b_i k_i
        for (int i4 = tid; i4 < (DSTATE * TM) / 4; i4 += NTH) {
            float4 y = reinterpret_cast<const float4*>(Y)[i4];
            float4 a = make_float4(0.f, 0.f, 0.f, 0.f);
            #pragma unroll
            for (int j = 0; j < 6; ++j) {
                float4 kv = reinterpret_cast<const float4*>(KB + j * DSTATE * TM)[i4];
                float bj = c_Bw[j];
                a.x += bj * kv.x; a.y += bj * kv.y;
                a.z += bj * kv.z; a.w += bj * kv.w;
            }
            y.x += H * a.x; y.y += H * a.y; y.z += H * a.z; y.w += H * a.w;
            reinterpret_cast<float4*>(Y)[i4] = y;
        }
        __syncthreads();
    }

    for (int idx = tid; idx < TM * DSTATE; idx += NTH) {
        int m = idx >> 8, c = idx & 255;
        out[(size_t)(r0 + m) * DSTATE + c] = Y[c * TM + m];
    }
}

// ---------------- launch ----------------
extern "C" void kernel_launch(void* const* d_in, const int* in_sizes, int n_in,
                              void* d_out, int out_size) {
    (void)in_sizes; (void)n_in; (void)out_size;
    const float* x0 = (const float*)d_in[0];
    const float* uf = (const float*)d_in[1];
    const float* W1 = (const float*)d_in[2];
    const float* b1 = (const float*)d_in[3];
    const float* W2 = (const float*)d_in[4];
    const float* b2 = (const float*)d_in[5];
    const float* W3 = (const float*)d_in[6];
    const float* b3 = (const float*)d_in[7];
    float* out = (float*)d_out;

    dim3 tthreads(32, 8);
    transpose_kernel<<<dim3(DIN / 32, NW / 32), tthreads>>>(0, W1, NW, DIN);
    transpose_kernel<<<dim3(NW / 32, NW / 32), tthreads>>>(1, W2, NW, NW);
    transpose_kernel<<<dim3(NW / 32, DSTATE / 32), tthreads>>>(2, W3, DSTATE, NW);

    size_t smem_bytes = (size_t)(3 * NW * TM + 7 * DSTATE * TM) * sizeof(float);
    cudaFuncSetAttribute(ode_main, cudaFuncAttributeMaxDynamicSharedMemorySize, (int)smem_bytes);
    ode_main<<<NBLOCKS, NTH, smem_bytes>>>(x0, uf, b1, b2, b3, out);
}

// round 11
// speedup vs baseline: 1.4295x; 1.0244x over previous
#include <cuda_runtime.h>

#define TM      16
#define NTH     256
#define DSTATE  256
#define DIN     512
#define NW      512
#define NSTEPS  60
#define NBLOCKS 128

typedef unsigned long long u64;

__constant__ float c_A[6][5] = {
    {0.f, 0.f, 0.f, 0.f, 0.f},
    {0.161f, 0.f, 0.f, 0.f, 0.f},
    {-0.008480655492356989f, 0.335480655492357f, 0.f, 0.f, 0.f},
    {2.8971530571054935f, -6.359448489975075f, 4.3622954328695815f, 0.f, 0.f},
    {5.325864828439257f, -11.748883564062828f, 7.4955393428898365f, -0.09249506636175525f, 0.f},
    {5.86145544294642f, -12.92096931784711f, 8.159367898576159f, -0.071584973281401f, -0.028269050394068383f}};
__constant__ float c_Bw[6] = {
    0.09646076681806523f, 0.01f, 0.4798896504144996f,
    1.379008574103742f, -3.290069515436081f, 2.324710524099774f};

// +4 rows of padding: the 4-deep prefetch overreads up to 4 k-rows at the
// loop tail (values never consumed).
__device__ float g_W1T[(DIN + 4) * NW];
__device__ float g_W2T[(NW + 4) * NW];
__device__ float g_W3T[(NW + 4) * DSTATE];
__device__ float g_BU[NBLOCKS * NW * TM];   // per-CTA b1 + W1[:,256:]@u

// ---------------- packed f32x2 helpers ----------------
static __device__ __forceinline__ u64 pk2(float x, float y) {
    u64 d; asm("mov.b64 %0, {%1, %2};" : "=l"(d) : "f"(x), "f"(y)); return d;
}
static __device__ __forceinline__ u64 fma2(u64 a, u64 b, u64 c) {
    u64 d; asm("fma.rn.f32x2 %0, %1, %2, %3;" : "=l"(d) : "l"(a), "l"(b), "l"(c)); return d;
}

// ---------------- weight transpose: src[N][K] -> dst[K][N] ----------------
__global__ void transpose_kernel(int which, const float* __restrict__ src, int N, int K) {
    float* dst = (which == 0) ? g_W1T : (which == 1) ? g_W2T : g_W3T;
    __shared__ float tile[32][33];
    int kb = blockIdx.x * 32, nb = blockIdx.y * 32;
    int tx = threadIdx.x, ty = threadIdx.y;
    #pragma unroll
    for (int i = ty; i < 32; i += 8) tile[i][tx] = src[(nb + i) * K + (kb + tx)];
    __syncthreads();
    #pragma unroll
    for (int i = ty; i < 32; i += 8) dst[(kb + i) * N + (nb + tx)] = tile[tx][i];
}

// ---------------- 8m x 8n register-tile GEMM, 4-deep A+W pipeline ----------
struct KB8 { float4 w0, w1; ulonglong2 a0, a1; };

static __device__ __forceinline__ KB8 ldk(const float* __restrict__ Asm,
                                          const float* __restrict__ Wg,
                                          int ldw, int k) {
    KB8 b;
    const float* wr = Wg + (size_t)k * ldw;
    b.w0 = *reinterpret_cast<const float4*>(wr);
    b.w1 = *reinterpret_cast<const float4*>(wr + 4);
    const float* ar = Asm + k * TM;
    b.a0 = *reinterpret_cast<const ulonglong2*>(ar);
    b.a1 = *reinterpret_cast<const ulonglong2*>(ar + 4);
    return b;
}

static __device__ __forceinline__ void cmp8(const KB8& b, u64* __restrict__ acc) {
    float wv[8] = {b.w0.x, b.w0.y, b.w0.z, b.w0.w, b.w1.x, b.w1.y, b.w1.z, b.w1.w};
    u64 ap0 = b.a0.x, ap1 = b.a0.y, ap2 = b.a1.x, ap3 = b.a1.y;
    #pragma unroll
    for (int nj = 0; nj < 8; ++nj) {
        u64 wd = pk2(wv[nj], wv[nj]);
        acc[nj * 4 + 0] = fma2(ap0, wd, acc[nj * 4 + 0]);
        acc[nj * 4 + 1] = fma2(ap1, wd, acc[nj * 4 + 1]);
        acc[nj * 4 + 2] = fma2(ap2, wd, acc[nj * 4 + 2]);
        acc[nj * 4 + 3] = fma2(ap3, wd, acc[nj * 4 + 3]);
    }
}

// KH must be a multiple of 4. Tail prefetch overreads up to 4 rows past KH in
// both Asm (lands in the adjacent live SMEM buffer) and Wg (padded arrays).
static __device__ __forceinline__ void mma8x8(
    const float* __restrict__ Asm, const float* __restrict__ Wg,
    int ldw, int KH, u64* __restrict__ acc) {
    KB8 b0 = ldk(Asm, Wg, ldw, 0);
    KB8 b1 = ldk(Asm, Wg, ldw, 1);
    KB8 b2 = ldk(Asm, Wg, ldw, 2);
    KB8 b3 = ldk(Asm, Wg, ldw, 3);
    #pragma unroll 1
    for (int k = 0; k < KH; k += 4) {
        cmp8(b0, acc); b0 = ldk(Asm, Wg, ldw, k + 4);
        cmp8(b1, acc); b1 = ldk(Asm, Wg, ldw, k + 5);
        cmp8(b2, acc); b2 = ldk(Asm, Wg, ldw, k + 6);
        cmp8(b3, acc); b3 = ldk(Asm, Wg, ldw, k + 7);
    }
}

static __device__ __forceinline__ void store_partial(
    float* __restrict__ dst, int n0, int m0, const u64* __restrict__ acc) {
    #pragma unroll
    for (int nj = 0; nj < 8; ++nj) {
        ulonglong2 v, w;
        v.x = acc[nj * 4 + 0]; v.y = acc[nj * 4 + 1];
        w.x = acc[nj * 4 + 2]; w.y = acc[nj * 4 + 3];
        *reinterpret_cast<ulonglong2*>(dst + (n0 + nj) * TM + m0) = v;
        *reinterpret_cast<ulonglong2*>(dst + (n0 + nj) * TM + m0 + 4) = w;
    }
}

static __device__ __forceinline__ void zero_acc(u64* acc) {
    #pragma unroll
    for (int i = 0; i < 32; ++i) acc[i] = 0ull;
}

// ---------------- main fused Tsit5 kernel ----------------
__global__ void __launch_bounds__(NTH, 1)
ode_main(const float* __restrict__ x0, const float* __restrict__ uf,
         const float* __restrict__ b1, const float* __restrict__ b2,
         const float* __restrict__ b3, float* __restrict__ out) {
    extern __shared__ float smem[];
    float* A0 = smem;                 // [512][16]
    float* A1 = A0 + NW * TM;         // [512][16]
    float* P  = A1 + NW * TM;         // [512][16]
    float* Y  = P + NW * TM;          // [256][16]
    float* KB = Y + DSTATE * TM;      // [6][256][16]

    const int tid = threadIdx.x;
    const int r0 = blockIdx.x * TM;
    float* BUg = g_BU + (size_t)blockIdx.x * (NW * TM);

    // N=512 gemms: 2-way k-split, 128 positions (2m x 64n)
    const int half = tid >> 7;
    const int pos = tid & 127;
    const int m0 = (pos & 1) * 8;
    const int n0 = (pos >> 1) * 8;
    // gemm3 (N=256): 4-way k-split, 64 positions
    const int q = tid >> 6;
    const int pos3 = tid & 63;
    const int m3 = (pos3 & 1) * 8;
    const int n3 = (pos3 >> 1) * 8;

    // init Y; u into A0 rows 0-255 (k-major) for BU precompute
    for (int idx = tid; idx < TM * DSTATE; idx += NTH) {
        int m = idx >> 8, c = idx & 255;
        int r = r0 + m, traj = r & 1023;
        Y[c * TM + m] = x0[traj * DSTATE + c];
        A0[c * TM + m] = (r < 1024) ? uf[traj * DSTATE + c] : 0.f;
    }
    __syncthreads();

    // ---- BU = b1 + W1[:,256:512] @ u ----
    {
        u64 acc[32];
        zero_acc(acc);
        mma8x8(A0 + half * 128 * TM + m0,
               g_W1T + (size_t)(DSTATE + half * 128) * NW + n0, NW, 128, acc);
        store_partial(half ? P : A1, n0, m0, acc);
        __syncthreads();
        for (int i4 = tid; i4 < (NW * TM) / 4; i4 += NTH) {
            float4 a = reinterpret_cast<const float4*>(A1)[i4];
            float4 p = reinterpret_cast<const float4*>(P)[i4];
            float bb = b1[i4 >> 2];
            reinterpret_cast<float4*>(BUg)[i4] =
                make_float4(a.x + p.x + bb, a.y + p.y + bb, a.z + p.z + bb, a.w + p.w + bb);
        }
        __syncthreads();
    }

    const float H = 1.0f / 60.0f;

    #pragma unroll 1
    for (int step = 0; step < NSTEPS; ++step) {
        #pragma unroll 1
        for (int s = 0; s < 6; ++s) {
            // z = y + H * sum_j a_sj k_j  -> A0 rows [0,256)
            for (int i4 = tid; i4 < (DSTATE * TM) / 4; i4 += NTH) {
                float4 y = reinterpret_cast<const float4*>(Y)[i4];
                float4 a = make_float4(0.f, 0.f, 0.f, 0.f);
                for (int j = 0; j < s; ++j) {
                    float4 kv = reinterpret_cast<const float4*>(KB + j * DSTATE * TM)[i4];
                    float aj = c_A[s][j];
                    a.x += aj * kv.x; a.y += aj * kv.y;
                    a.z += aj * kv.z; a.w += aj * kv.w;
                }
                y.x += H * a.x; y.y += H * a.y; y.z += H * a.z; y.w += H * a.w;
                reinterpret_cast<float4*>(A0)[i4] = y;
            }
            __syncthreads();

            // gemm1: A1 = relu(BU + W1[:, :256] @ z), K=256, 2-way k-split
            {
                u64 acc[32];
                zero_acc(acc);
                mma8x8(A0 + half * 128 * TM + m0,
                       g_W1T + (size_t)(half * 128) * NW + n0, NW, 128, acc);
                store_partial(half ? P : A1, n0, m0, acc);
                __syncthreads();
                for (int i4 = tid; i4 < (NW * TM) / 4; i4 += NTH) {
                    float4 a = reinterpret_cast<const float4*>(A1)[i4];
                    float4 p = reinterpret_cast<const float4*>(P)[i4];
                    float4 bu = reinterpret_cast<const float4*>(BUg)[i4];
                    float4 v;
                    v.x = fmaxf(a.x + p.x + bu.x, 0.f);
                    v.y = fmaxf(a.y + p.y + bu.y, 0.f);
                    v.z = fmaxf(a.z + p.z + bu.z, 0.f);
                    v.w = fmaxf(a.w + p.w + bu.w, 0.f);
                    reinterpret_cast<float4*>(A1)[i4] = v;
                }
                __syncthreads();
            }
            // gemm2: A0 = relu(b2 + W2 @ h1), K=512, 2-way k-split
            {
                u64 acc[32];
                zero_acc(acc);
                mma8x8(A1 + half * 256 * TM + m0,
                       g_W2T + (size_t)(half * 256) * NW + n0, NW, 256, acc);
                store_partial(half ? P : A0, n0, m0, acc);
                __syncthreads();
                for (int i4 = tid; i4 < (NW * TM) / 4; i4 += NTH) {
                    float4 a = reinterpret_cast<const float4*>(A0)[i4];
                    float4 p = reinterpret_cast<const float4*>(P)[i4];
                    float bb = b2[i4 >> 2];
                    float4 v;
                    v.x = fmaxf(a.x + p.x + bb, 0.f);
                    v.y = fmaxf(a.y + p.y + bb, 0.f);
                    v.z = fmaxf(a.z + p.z + bb, 0.f);
                    v.w = fmaxf(a.w + p.w + bb, 0.f);
                    reinterpret_cast<float4*>(A0)[i4] = v;
                }
                __syncthreads();
            }
            // gemm3: k_s = b3 + W3 @ h2, K=512, N=256, 4-way k-split
            {
                float* KBs = KB + s * DSTATE * TM;
                u64 acc[32];
                zero_acc(acc);
                mma8x8(A0 + q * 128 * TM + m3,
                       g_W3T + (size_t)(q * 128) * DSTATE + n3, DSTATE, 128, acc);
                float* pdst = (q == 0) ? KBs : (q == 1) ? P : (q == 2) ? (P + DSTATE * TM) : A1;
                store_partial(pdst, n3, m3, acc);
                __syncthreads();
                for (int i4 = tid; i4 < (DSTATE * TM) / 4; i4 += NTH) {
                    float4 a  = reinterpret_cast<const float4*>(KBs)[i4];
                    float4 p1 = reinterpret_cast<const float4*>(P)[i4];
                    float4 p2 = reinterpret_cast<const float4*>(P + DSTATE * TM)[i4];
                    float4 p3 = reinterpret_cast<const float4*>(A1)[i4];
                    float bb = b3[i4 >> 2];
                    float4 v;
                    v.x = a.x + p1.x + p2.x + p3.x + bb;
                    v.y = a.y + p1.y + p2.y + p3.y + bb;
                    v.z = a.z + p1.z + p2.z + p3.z + bb;
                    v.w = a.w + p1.w + p2.w + p3.w + bb;
                    reinterpret_cast<float4*>(KBs)[i4] = v;
                }
                __syncthreads();
            }
        }
        // y += H * sum_i b_i k_i
        for (int i4 = tid; i4 < (DSTATE * TM) / 4; i4 += NTH) {
            float4 y = reinterpret_cast<const float4*>(Y)[i4];
            float4 a = make_float4(0.f, 0.f, 0.f, 0.f);
            #pragma unroll
            for (int j = 0; j < 6; ++j) {
                float4 kv = reinterpret_cast<const float4*>(KB + j * DSTATE * TM)[i4];
                float bj = c_Bw[j];
                a.x += bj * kv.x; a.y += bj * kv.y;
                a.z += bj * kv.z; a.w += bj * kv.w;
            }
            y.x += H * a.x; y.y += H * a.y; y.z += H * a.z; y.w += H * a.w;
            reinterpret_cast<float4*>(Y)[i4] = y;
        }
        __syncthreads();
    }

    for (int idx = tid; idx < TM * DSTATE; idx += NTH) {
        int m = idx >> 8, c = idx & 255;
        out[(size_t)(r0 + m) * DSTATE + c] = Y[c * TM + m];
    }
}

// ---------------- launch ----------------
extern "C" void kernel_launch(void* const* d_in, const int* in_sizes, int n_in,
                              void* d_out, int out_size) {
    (void)in_sizes; (void)n_in; (void)out_size;
    const float* x0 = (const float*)d_in[0];
    const float* uf = (const float*)d_in[1];
    const float* W1 = (const float*)d_in[2];
    const float* b1 = (const float*)d_in[3];
    const float* W2 = (const float*)d_in[4];
    const float* b2 = (const float*)d_in[5];
    const float* W3 = (const float*)d_in[6];
    const float* b3 = (const float*)d_in[7];
    float* out = (float*)d_out;

    dim3 tthreads(32, 8);
    transpose_kernel<<<dim3(DIN / 32, NW / 32), tthreads>>>(0, W1, NW, DIN);
    transpose_kernel<<<dim3(NW / 32, NW / 32), tthreads>>>(1, W2, NW, NW);
    transpose_kernel<<<dim3(NW / 32, DSTATE / 32), tthreads>>>(2, W3, DSTATE, NW);

    size_t smem_bytes = (size_t)(3 * NW * TM + 7 * DSTATE * TM) * sizeof(float);
    cudaFuncSetAttribute(ode_main, cudaFuncAttributeMaxDynamicSharedMemorySize, (int)smem_bytes);
    ode_main<<<NBLOCKS, NTH, smem_bytes>>>(x0, uf, b1, b2, b3, out);
}